// round 6
// baseline (speedup 1.0000x reference)
#include <cuda_runtime.h>
#include <cuda_fp16.h>

#define Bn 4
#define Cn 32
#define Hn 512
#define Wn 512
#define HWn (Hn * Wn)
#define PSTRIP 128           // pixels per gather strip / transpose tile
#define SMEM_BYTES 20992     // max(gather: 2048+2048+16896, transpose: 16896)

// Two 16MB NHWC fp16 scratch buffers (double-buffered across batches; L2-resident)
__device__ __half g_xt[2][(size_t)HWn * Cn];

// ---------------------------------------------------------------------------
// Transpose one 128w x 32c tile of NCHW fp32 -> NHWC fp16 at row h.
// 4 independent float4 loads per thread; 2 uint4 stores per thread.
// ---------------------------------------------------------------------------
__device__ __forceinline__ void transpose_tile(const float* __restrict__ xb,
                                               __half* __restrict__ dst,
                                               char* sm, int w0, int h, int tid)
{
    float* tile = (float*)sm;            // [128][33]
#pragma unroll
    for (int iter = 0; iter < 4; ++iter) {
        const int c  = iter * 8 + (tid >> 5);
        const int wq = tid & 31;
        const float4 v = __ldg((const float4*)(
            xb + (size_t)c * HWn + h * Wn + w0 + wq * 4));
        float* t = tile + (wq * 4) * 33 + c;
        t[0]  = v.x;
        t[33] = v.y;
        t[66] = v.z;
        t[99] = v.w;
    }
    __syncthreads();

    // thread (pix = tid>>1, part = tid&1) -> 16 channels -> two uint4 stores
    const int pix  = tid >> 1;
    const int part = tid & 1;
    const float* row = tile + pix * 33 + part * 16;
    __half2 hh[8];
#pragma unroll
    for (int j = 0; j < 8; ++j)
        hh[j] = __floats2half2_rn(row[2 * j], row[2 * j + 1]);
    uint4 u0, u1;
    u0.x = *(const unsigned int*)&hh[0];
    u0.y = *(const unsigned int*)&hh[1];
    u0.z = *(const unsigned int*)&hh[2];
    u0.w = *(const unsigned int*)&hh[3];
    u1.x = *(const unsigned int*)&hh[4];
    u1.y = *(const unsigned int*)&hh[5];
    u1.z = *(const unsigned int*)&hh[6];
    u1.w = *(const unsigned int*)&hh[7];
    char* p = (char*)(dst + ((size_t)(h * Wn) + w0 + pix) * Cn) + part * 32;
    *(uint4*)p        = u0;
    *(uint4*)(p + 16) = u1;
    __syncthreads();
}

// ---------------------------------------------------------------------------
// Gather one 128-pixel w-strip at row h from NHWC fp16 src; residual-add +
// coalesced NCHW fp32 store. 8 independent uint4 gathers per thread.
// ---------------------------------------------------------------------------
__device__ __forceinline__ void gather_strip(const __half* __restrict__ src,
                                             const float* __restrict__ flowb,
                                             const float* __restrict__ residualb,
                                             float* __restrict__ outb,
                                             char* sm, int w0, int h, int tid)
{
    float* s_wt = (float*)sm;                 // [4][128]
    int*   s_of = (int*)(sm + 2048);          // [4][128]
    float* sres = (float*)(sm + 4096);        // [128][33]

    // ---- phase 0: per-pixel sampling params (128 threads) ----
    if (tid < PSTRIP) {
        const int w = w0 + tid;
        const int pix = h * Wn + w;
        const float fx = __ldg(flowb + pix);
        const float fy = __ldg(flowb + HWn + pix);

        float gx = (w + 0.5f) * (2.0f / Wn) - 1.0f + fx;
        float gy = (h + 0.5f) * (2.0f / Hn) - 1.0f + fy;

        // circular wrap on x: mod(gx+1, 2) - 1
        float t = gx + 1.0f;
        t = t - floorf(t * 0.5f) * 2.0f;
        gx = t - 1.0f;

        const float rx = (gx + 1.0f) * (Wn * 0.5f) - 0.5f;
        const float ry = (gy + 1.0f) * (Hn * 0.5f) - 0.5f;

        const float x0f = floorf(rx);
        const float y0f = floorf(ry);
        const float dx = rx - x0f;
        const float dy = ry - y0f;

        const int ix0 = (int)x0f, iy0 = (int)y0f;
        const int ix1 = ix0 + 1,  iy1 = iy0 + 1;

        const float vx0 = (ix0 >= 0 && ix0 < Wn) ? 1.0f : 0.0f;
        const float vx1 = (ix1 >= 0 && ix1 < Wn) ? 1.0f : 0.0f;
        const float vy0 = (iy0 >= 0 && iy0 < Hn) ? 1.0f : 0.0f;
        const float vy1 = (iy1 >= 0 && iy1 < Hn) ? 1.0f : 0.0f;

        s_wt[0 * PSTRIP + tid] = (1.0f - dx) * (1.0f - dy) * vx0 * vy0;
        s_wt[1 * PSTRIP + tid] = dx * (1.0f - dy) * vx1 * vy0;
        s_wt[2 * PSTRIP + tid] = (1.0f - dx) * dy * vx0 * vy1;
        s_wt[3 * PSTRIP + tid] = dx * dy * vx1 * vy1;

        const int cx0 = min(max(ix0, 0), Wn - 1);
        const int cx1 = min(max(ix1, 0), Wn - 1);
        const int cy0 = min(max(iy0, 0), Hn - 1);
        const int cy1 = min(max(iy1, 0), Hn - 1);
        s_of[0 * PSTRIP + tid] = cy0 * Wn + cx0;
        s_of[1 * PSTRIP + tid] = cy0 * Wn + cx1;
        s_of[2 * PSTRIP + tid] = cy1 * Wn + cx0;
        s_of[3 * PSTRIP + tid] = cy1 * Wn + cx1;
    }
    __syncthreads();

    // ---- phase 1: gather. thread = (pixel i, 16-channel half) ----
    {
        const int i    = tid >> 1;   // 0..127
        const int half = tid & 1;    // channels half*16 .. +15
        const __half* xb = src + half * 16;

        // issue all 8 gathers before consuming (max MLP)
        uint4 ld[8];
#pragma unroll
        for (int cnr = 0; cnr < 4; ++cnr) {
            const uint4* p = (const uint4*)(xb + (size_t)s_of[cnr * PSTRIP + i] * Cn);
            ld[2 * cnr + 0] = __ldg(p);
            ld[2 * cnr + 1] = __ldg(p + 1);
        }

        float r[16];
#pragma unroll
        for (int k = 0; k < 16; ++k) r[k] = 0.0f;

#pragma unroll
        for (int cnr = 0; cnr < 4; ++cnr) {
            const float wt = s_wt[cnr * PSTRIP + i];
            const unsigned int uu[8] = {
                ld[2 * cnr].x, ld[2 * cnr].y, ld[2 * cnr].z, ld[2 * cnr].w,
                ld[2 * cnr + 1].x, ld[2 * cnr + 1].y, ld[2 * cnr + 1].z, ld[2 * cnr + 1].w };
#pragma unroll
            for (int j = 0; j < 8; ++j) {
                const float2 f = __half22float2(*(const __half2*)&uu[j]);
                r[j * 2 + 0] += wt * f.x;
                r[j * 2 + 1] += wt * f.y;
            }
        }

        float* s = sres + i * 33 + half * 16;
#pragma unroll
        for (int k = 0; k < 16; ++k) s[k] = r[k];
    }
    __syncthreads();

    // ---- phase 2: conflict-free scalar residual-add + coalesced NCHW store ----
    {
        const int wi = tid & 127;   // pixel within strip
        const int cg = tid >> 7;    // 0..1 -> channels cg*16 .. +15
        const size_t base = (size_t)(h * Wn) + w0 + wi;
#pragma unroll
        for (int k = 0; k < 16; ++k) {
            const int c = cg * 16 + k;
            const size_t o = base + (size_t)c * HWn;
            outb[o] = sres[wi * 33 + c] + __ldg(residualb + o);
        }
    }
    __syncthreads();
}

// ---------------------------------------------------------------------------
// Kernels
// ---------------------------------------------------------------------------
__global__ __launch_bounds__(256) void transpose_kernel(
    const float* __restrict__ xb, int dstsel)
{
    __shared__ char sm[SMEM_BYTES];
    transpose_tile(xb, g_xt[dstsel], sm, blockIdx.x * PSTRIP, blockIdx.y, threadIdx.x);
}

__global__ __launch_bounds__(256) void gather_kernel(
    const float* __restrict__ flowb, const float* __restrict__ residualb,
    float* __restrict__ outb, int srcsel)
{
    __shared__ char sm[SMEM_BYTES];
    gather_strip(g_xt[srcsel], flowb, residualb, outb, sm,
                 blockIdx.x * PSTRIP, blockIdx.y, threadIdx.x);
}

// Fused: gather(batch b from buffer gsel) + transpose(batch b+1 -> gsel^1)
__global__ __launch_bounds__(256) void fused_kernel(
    const float* __restrict__ xnext,
    const float* __restrict__ flowb, const float* __restrict__ residualb,
    float* __restrict__ outb, int gsel)
{
    __shared__ char sm[SMEM_BYTES];
    const int bx = blockIdx.x >> 1;
    if (blockIdx.x & 1)
        transpose_tile(xnext, g_xt[gsel ^ 1], sm, bx * PSTRIP, blockIdx.y, threadIdx.x);
    else
        gather_strip(g_xt[gsel], flowb, residualb, outb, sm,
                     bx * PSTRIP, blockIdx.y, threadIdx.x);
}

extern "C" void kernel_launch(void* const* d_in, const int* in_sizes, int n_in,
                              void* d_out, int out_size)
{
    const float* x        = (const float*)d_in[0];
    const float* flow     = (const float*)d_in[1];
    const float* residual = (const float*)d_in[2];
    float*       out      = (float*)d_out;

    dim3 gridT(Wn / PSTRIP, Hn);
    dim3 gridG(Wn / PSTRIP, Hn);
    dim3 gridF(2 * (Wn / PSTRIP), Hn);

    // pipeline: T(0), [G(b) || T(b+1)] for b=0..2, G(3)
    transpose_kernel<<<gridT, 256>>>(x, 0);
    for (int b = 0; b < Bn - 1; ++b) {
        fused_kernel<<<gridF, 256>>>(x + (size_t)(b + 1) * Cn * HWn,
                                     flow + (size_t)b * 2 * HWn,
                                     residual + (size_t)b * Cn * HWn,
                                     out + (size_t)b * Cn * HWn,
                                     b & 1);
    }
    gather_kernel<<<gridG, 256>>>(flow + (size_t)(Bn - 1) * 2 * HWn,
                                  residual + (size_t)(Bn - 1) * Cn * HWn,
                                  out + (size_t)(Bn - 1) * Cn * HWn,
                                  (Bn - 1) & 1);
}

// round 7
// speedup vs baseline: 1.2004x; 1.2004x over previous
#include <cuda_runtime.h>
#include <cuda_fp16.h>

#define Bn 4
#define Cn 32
#define Hn 512
#define Wn 512
#define HWn (Hn * Wn)
#define PSTRIP 64

// NHWC fp16 scratch copy of x: [B][H][W][C] = 64 MB
__device__ __half g_xt[(size_t)Bn * HWn * Cn];

// ---------------------------------------------------------------------------
// Pass 1: NCHW fp32 -> NHWC fp16. Block = 128 w x 32 c tile at fixed (b,h).
// 4 independent float4 loads per thread; 2 uint4 stores per thread.
// ---------------------------------------------------------------------------
__global__ __launch_bounds__(256) void transpose_kernel(const float* __restrict__ x)
{
    __shared__ float tile[128 * 33];
    const int w0 = blockIdx.x * 128;
    const int h  = blockIdx.y;
    const int b  = blockIdx.z;
    const int tid = threadIdx.x;

    const float* xb = x + (size_t)b * Cn * HWn + h * Wn + w0;
#pragma unroll
    for (int iter = 0; iter < 4; ++iter) {
        const int c  = iter * 8 + (tid >> 5);
        const int wq = tid & 31;
        const float4 v = __ldg((const float4*)(xb + (size_t)c * HWn + wq * 4));
        float* t = tile + (wq * 4) * 33 + c;
        t[0]  = v.x;
        t[33] = v.y;
        t[66] = v.z;
        t[99] = v.w;
    }
    __syncthreads();

    // store: thread (pix = tid>>1, part = tid&1) -> 16 channels -> 2 uint4
    const int pix  = tid >> 1;
    const int part = tid & 1;
    const float* row = tile + pix * 33 + part * 16;
    __half2 hh[8];
#pragma unroll
    for (int j = 0; j < 8; ++j)
        hh[j] = __floats2half2_rn(row[2 * j], row[2 * j + 1]);
    uint4 u0, u1;
    u0.x = *(const unsigned int*)&hh[0];
    u0.y = *(const unsigned int*)&hh[1];
    u0.z = *(const unsigned int*)&hh[2];
    u0.w = *(const unsigned int*)&hh[3];
    u1.x = *(const unsigned int*)&hh[4];
    u1.y = *(const unsigned int*)&hh[5];
    u1.z = *(const unsigned int*)&hh[6];
    u1.w = *(const unsigned int*)&hh[7];
    char* p = (char*)(g_xt + (((size_t)b * Hn + h) * Wn + w0 + pix) * Cn) + part * 32;
    *(uint4*)p        = u0;
    *(uint4*)(p + 16) = u1;
}

// ---------------------------------------------------------------------------
// Pass 2: per-pixel params once (smem broadcast), fp16 NHWC gathers with
// 4 lanes x 16B per pixel, smem transpose, coalesced residual-add + NCHW store.
// Block = 64-pixel w-strip at fixed (b,h).   [identical to the 102.9us winner]
// ---------------------------------------------------------------------------
__global__ __launch_bounds__(256) void warp_gather_kernel(
    const float* __restrict__ flow,
    const float* __restrict__ residual,
    float* __restrict__ out)
{
    __shared__ float s_wt[4][PSTRIP];   // tl,tr,bl,br weights
    __shared__ int   s_of[4][PSTRIP];   // tl,tr,bl,br pixel offsets
    __shared__ float sres[PSTRIP * 33]; // [pixel][channel]

    const int w0  = blockIdx.x * PSTRIP;
    const int h   = blockIdx.y;
    const int b   = blockIdx.z;
    const int tid = threadIdx.x;

    // ---- phase 0: 64 threads compute per-pixel sampling params ----
    if (tid < PSTRIP) {
        const int w = w0 + tid;
        const int pix = h * Wn + w;
        const float* fb = flow + (size_t)b * 2 * HWn;
        const float fx = __ldg(fb + pix);
        const float fy = __ldg(fb + HWn + pix);

        float gx = (w + 0.5f) * (2.0f / Wn) - 1.0f + fx;
        float gy = (h + 0.5f) * (2.0f / Hn) - 1.0f + fy;

        // circular wrap on x: mod(gx+1, 2) - 1
        float t = gx + 1.0f;
        t = t - floorf(t * 0.5f) * 2.0f;
        gx = t - 1.0f;

        const float rx = (gx + 1.0f) * (Wn * 0.5f) - 0.5f;
        const float ry = (gy + 1.0f) * (Hn * 0.5f) - 0.5f;

        const float x0f = floorf(rx);
        const float y0f = floorf(ry);
        const float dx = rx - x0f;
        const float dy = ry - y0f;

        const int ix0 = (int)x0f, iy0 = (int)y0f;
        const int ix1 = ix0 + 1,  iy1 = iy0 + 1;

        const float vx0 = (ix0 >= 0 && ix0 < Wn) ? 1.0f : 0.0f;
        const float vx1 = (ix1 >= 0 && ix1 < Wn) ? 1.0f : 0.0f;
        const float vy0 = (iy0 >= 0 && iy0 < Hn) ? 1.0f : 0.0f;
        const float vy1 = (iy1 >= 0 && iy1 < Hn) ? 1.0f : 0.0f;

        s_wt[0][tid] = (1.0f - dx) * (1.0f - dy) * vx0 * vy0;
        s_wt[1][tid] = dx * (1.0f - dy) * vx1 * vy0;
        s_wt[2][tid] = (1.0f - dx) * dy * vx0 * vy1;
        s_wt[3][tid] = dx * dy * vx1 * vy1;

        const int cx0 = min(max(ix0, 0), Wn - 1);
        const int cx1 = min(max(ix1, 0), Wn - 1);
        const int cy0 = min(max(iy0, 0), Hn - 1);
        const int cy1 = min(max(iy1, 0), Hn - 1);
        s_of[0][tid] = cy0 * Wn + cx0;
        s_of[1][tid] = cy0 * Wn + cx1;
        s_of[2][tid] = cy1 * Wn + cx0;
        s_of[3][tid] = cy1 * Wn + cx1;
    }
    __syncthreads();

    // ---- phase 1: gather. thread = (pixel i, 8-channel group q) ----
    {
        const int i = tid >> 2;     // 0..63
        const int q = tid & 3;      // 0..3 (channels q*8 .. q*8+7)
        const __half* xb = g_xt + (size_t)b * HWn * Cn + q * 8;

        float r[8];
#pragma unroll
        for (int k = 0; k < 8; ++k) r[k] = 0.0f;

#pragma unroll
        for (int cnr = 0; cnr < 4; ++cnr) {
            const float wt = s_wt[cnr][i];
            const uint4 ld = __ldg((const uint4*)(xb + (size_t)s_of[cnr][i] * Cn));
            const unsigned int uu[4] = {ld.x, ld.y, ld.z, ld.w};
#pragma unroll
            for (int j = 0; j < 4; ++j) {
                const float2 f = __half22float2(*(const __half2*)&uu[j]);
                r[j * 2 + 0] += wt * f.x;
                r[j * 2 + 1] += wt * f.y;
            }
        }

        float* s = sres + i * 33 + q * 8;
#pragma unroll
        for (int k = 0; k < 8; ++k) s[k] = r[k];
    }
    __syncthreads();

    // ---- phase 2: coalesced residual-add + NCHW store ----
    {
        const int wi = tid & 63;    // 0..63
        const int cg = tid >> 6;    // 0..3
        const size_t base = (size_t)b * Cn * HWn + h * Wn + w0 + wi;
#pragma unroll
        for (int cc = 0; cc < 32; cc += 4) {
            const int c = cc + cg;
            const size_t o = base + (size_t)c * HWn;
            out[o] = sres[wi * 33 + c] + __ldg(residual + o);
        }
    }
}

extern "C" void kernel_launch(void* const* d_in, const int* in_sizes, int n_in,
                              void* d_out, int out_size)
{
    const float* x        = (const float*)d_in[0];
    const float* flow     = (const float*)d_in[1];
    const float* residual = (const float*)d_in[2];
    float*       out      = (float*)d_out;

    dim3 gridT(Wn / 128, Hn, Bn);
    transpose_kernel<<<gridT, 256>>>(x);
    dim3 gridG(Wn / PSTRIP, Hn, Bn);
    warp_gather_kernel<<<gridG, 256>>>(flow, residual, out);
}